// round 9
// baseline (speedup 1.0000x reference)
#include <cuda_runtime.h>
#include <cuda_bf16.h>

#define NB      8192
#define STEPS   50
#define HID     64

__device__ float    g_c0[NB];     // NN result
__device__ unsigned g_ctr;        // work-stealing counter (reset by nn_kernel)

// ---------------------------------------------------------------------------
// Kernel 1: smem-staged 1-D nearest neighbor, one warp per sample.
// Interleaved float2 scan, two compare chains, lexicographic merge ->
// exact argmin-first-index semantics of the reference (CD=1: norm == abs).
// Also resets the work-stealing counter for the solve kernel (stream-ordered).
// ---------------------------------------------------------------------------
__global__ void __launch_bounds__(256) nn_kernel(const float* __restrict__ c, int B)
{
    __shared__ __align__(16) float sc[NB];
    const int tid = threadIdx.x;
    {
        const float4* c4 = (const float4*)c;
        float4* s4 = (float4*)sc;
        #pragma unroll
        for (int i = 0; i < NB / 4 / 256; ++i) s4[tid + i * 256] = c4[tid + i * 256];
    }
    if (blockIdx.x == 0 && tid == 0) g_ctr = 0u;   // reset for solve kernel
    __syncthreads();

    const int w = tid >> 5, l = tid & 31;
    const int smp = blockIdx.x * 8 + w;
    if (smp >= B) return;

    const float ci = sc[smp];
    const float2* sc2 = (const float2*)sc;
    float bx = 3.0e38f, by = 3.0e38f;
    int   jx = 0,       jy = 1;
    #pragma unroll 4
    for (int q = 0; q < NB / 64; ++q) {
        float2 v = sc2[q * 32 + l];
        int j = (q * 32 + l) * 2;
        float dx = fabsf(ci - v.x); if (j == smp)     dx = 3.0e38f;
        if (dx < bx) { bx = dx; jx = j; }
        float dy = fabsf(ci - v.y); if (j + 1 == smp) dy = 3.0e38f;
        if (dy < by) { by = dy; jy = j + 1; }
    }
    float best = bx; int bj = jx;
    if (by < best || (by == best && jy < bj)) { best = by; bj = jy; }
    #pragma unroll
    for (int off = 16; off; off >>= 1) {
        float ob = __shfl_xor_sync(0xffffffffu, best, off);
        int   oj = __shfl_xor_sync(0xffffffffu, bj,   off);
        if (ob < best || (ob == best && oj < bj)) { best = ob; bj = oj; }
    }
    if (l == 0) g_c0[smp] = sc[bj];
}

// ---------------------------------------------------------------------------
// Kernel 2: PERSISTENT warp-per-sample solve with work stealing.
// Grid = one full residency wave; each warp atomically pulls sample ids.
// Per-sample math identical to R8 (piecewise-linear affine caching + rank-1
// incremental mask updates; float4-packed weights, bit-identical results).
// ---------------------------------------------------------------------------
__global__ void __launch_bounds__(256, 5) solve_kernel(
    const float* __restrict__ x,
    const float* __restrict__ W1, const float* __restrict__ b1,
    const float* __restrict__ W2, const float* __restrict__ b2,
    const float* __restrict__ W3, const float* __restrict__ b3,
    const float* __restrict__ W4,
    float* __restrict__ out, int B)
{
    __shared__ __align__(16) float4 pW2f4[HID * 16];   // 16 KB
    __shared__ __align__(16) float4 pW3f4[HID * 16];   // 16 KB
    __shared__ float4 sAct4[8][HID / 2];               // 4 KB

    const int tid = threadIdx.x;
    for (int idx = tid; idx < HID * HID; idx += 256) {
        int o = idx >> 6, k = idx & 63;
        int slot = (k >> 1) * 32 + (o & 31);
        int comp = (k & 1) * 2 + (o >> 5);     // [lo2q, hi2q, lo2q1, hi2q1]
        ((float*)&pW2f4[slot])[comp] = W2[idx];
        ((float*)&pW3f4[slot])[comp] = W3[idx];
    }
    __syncthreads();

    const int w = tid >> 5, l = tid & 31;
    const int o0 = l, o1 = l + 32;

    // warp-invariant per-lane weight constants (loaded once)
    const float w1xlo = W1[o0 * 3 + 0], w1clo = W1[o0 * 3 + 2];
    const float w1xhi = W1[o1 * 3 + 0], w1chi = W1[o1 * 3 + 2];
    const float wylo  = W1[o0 * 3 + 1], wyhi  = W1[o1 * 3 + 1];
    const float b1lo  = b1[o0], b1hi = b1[o1];
    const float b2lo  = b2[o0], b2hi = b2[o1];
    const float b3lo  = b3[o0], b3hi = b3[o1];
    const float w4lo  = W4[o0], w4hi = W4[o1];

    float2* act = (float2*)sAct4[w];
    const float4* act4 = (const float4*)sAct4[w];

    for (;;) {
        // ---- steal next sample ----
        unsigned my = 0u;
        if (l == 0) my = atomicAdd(&g_ctr, 1u);
        my = __shfl_sync(0xffffffffu, my, 0);
        if (my >= (unsigned)B) break;
        const int smp = (int)my;

        const float xi  = x[smp];
        const float c0i = g_c0[smp];
        const float a1lo = __fmaf_rn(w1xlo, xi, __fmaf_rn(w1clo, c0i, b1lo));
        const float a1hi = __fmaf_rn(w1xhi, xi, __fmaf_rn(w1chi, c0i, b1hi));

        float y = 0.0f;                       // Y_MEAN
        float t0 = 0.f, t1 = 0.f, ub0 = 0.f, ub1 = 0.f;   // ub includes +b2
        float s0 = 0.f, s1 = 0.f, rb0 = 0.f, rb1 = 0.f;   // rb includes +b3
        float gy = 0.0f;
        unsigned prevpk = 0u;
        bool force = true;

        for (int step = 0; step < STEPS; ++step) {
            // speculative affine evaluation (exact while masks unchanged)
            float z1lo = __fmaf_rn(y, wylo, a1lo);
            float z1hi = __fmaf_rn(y, wyhi, a1hi);
            float z2lo = __fmaf_rn(y, t0, ub0);
            float z2hi = __fmaf_rn(y, t1, ub1);
            float z3lo = __fmaf_rn(y, s0, rb0);
            float z3hi = __fmaf_rn(y, s1, rb1);

            unsigned pk = (unsigned)(z1lo > 0.0f)
                        | ((unsigned)(z1hi > 0.0f) << 1)
                        | ((unsigned)(z2lo > 0.0f) << 2)
                        | ((unsigned)(z2hi > 0.0f) << 3)
                        | ((unsigned)(z3lo > 0.0f) << 4)
                        | ((unsigned)(z3hi > 0.0f) << 5);

            unsigned any = __ballot_sync(0xffffffffu, force | (pk != prevpk));
            if (any) {
                const unsigned d = pk ^ prevpk;

                // ---------- level 1 ----------
                unsigned f1a = __ballot_sync(0xffffffffu, (d & 1u) != 0u);
                unsigned f1b = __ballot_sync(0xffffffffu, (d & 2u) != 0u);
                int n1 = __popc(f1a) + __popc(f1b);
                bool full1 = force || (n1 > 6);
                if (full1) {
                    bool p0 = z1lo > 0.0f, p1 = z1hi > 0.0f;
                    act[o0] = make_float2(p0 ? a1lo : 0.0f, p0 ? wylo : 0.0f);
                    act[o1] = make_float2(p1 ? a1hi : 0.0f, p1 ? wyhi : 0.0f);
                    __syncwarp();
                    float u0 = 0.f, u1 = 0.f;
                    t0 = t1 = 0.f;
                    #pragma unroll 8
                    for (int q = 0; q < 32; ++q) {
                        float4 a  = act4[q];
                        float4 wv = pW2f4[q * 32 + l];
                        u0 = __fmaf_rn(wv.x, a.x, u0); u1 = __fmaf_rn(wv.y, a.x, u1);
                        t0 = __fmaf_rn(wv.x, a.y, t0); t1 = __fmaf_rn(wv.y, a.y, t1);
                        u0 = __fmaf_rn(wv.z, a.z, u0); u1 = __fmaf_rn(wv.w, a.z, u1);
                        t0 = __fmaf_rn(wv.z, a.w, t0); t1 = __fmaf_rn(wv.w, a.w, t1);
                    }
                    __syncwarp();
                    ub0 = u0 + b2lo;
                    ub1 = u1 + b2hi;
                } else if (n1) {
                    // rank-1 AXPY per flipped m1 bit (sign = NEW state)
                    float sa_lo = (z1lo > 0.0f) ? a1lo : -a1lo;
                    float st_lo = (z1lo > 0.0f) ? wylo : -wylo;
                    float sa_hi = (z1hi > 0.0f) ? a1hi : -a1hi;
                    float st_hi = (z1hi > 0.0f) ? wyhi : -wyhi;
                    for (unsigned m = f1a; m; m &= m - 1u) {
                        int k = __ffs(m) - 1;
                        float ca = __shfl_sync(0xffffffffu, sa_lo, k);
                        float ct = __shfl_sync(0xffffffffu, st_lo, k);
                        float4 wv = pW2f4[(k >> 1) * 32 + l];
                        float wxc = (k & 1) ? wv.z : wv.x;
                        float wyc = (k & 1) ? wv.w : wv.y;
                        ub0 = __fmaf_rn(ca, wxc, ub0); ub1 = __fmaf_rn(ca, wyc, ub1);
                        t0  = __fmaf_rn(ct, wxc, t0);  t1  = __fmaf_rn(ct, wyc, t1);
                    }
                    for (unsigned m = f1b; m; m &= m - 1u) {
                        int kk = (__ffs(m) - 1) + 32;
                        float ca = __shfl_sync(0xffffffffu, sa_hi, kk - 32);
                        float ct = __shfl_sync(0xffffffffu, st_hi, kk - 32);
                        float4 wv = pW2f4[(kk >> 1) * 32 + l];
                        float wxc = (kk & 1) ? wv.z : wv.x;
                        float wyc = (kk & 1) ? wv.w : wv.y;
                        ub0 = __fmaf_rn(ca, wxc, ub0); ub1 = __fmaf_rn(ca, wyc, ub1);
                        t0  = __fmaf_rn(ct, wxc, t0);  t1  = __fmaf_rn(ct, wyc, t1);
                    }
                }
                const bool l1ran = full1 || (n1 > 0);
                if (l1ran) {
                    z2lo = __fmaf_rn(y, t0, ub0);
                    z2hi = __fmaf_rn(y, t1, ub1);
                }

                // ---------- level 2 ----------
                bool q0 = z2lo > 0.0f, q1 = z2hi > 0.0f;
                if (l1ran) {
                    act[o0] = make_float2(q0 ? ub0 : 0.0f, q0 ? t0 : 0.0f);
                    act[o1] = make_float2(q1 ? ub1 : 0.0f, q1 ? t1 : 0.0f);
                    __syncwarp();
                    float r0 = 0.f, r1 = 0.f;
                    s0 = s1 = 0.f;
                    #pragma unroll 8
                    for (int q = 0; q < 32; ++q) {
                        float4 a  = act4[q];
                        float4 wv = pW3f4[q * 32 + l];
                        r0 = __fmaf_rn(wv.x, a.x, r0); r1 = __fmaf_rn(wv.y, a.x, r1);
                        s0 = __fmaf_rn(wv.x, a.y, s0); s1 = __fmaf_rn(wv.y, a.y, s1);
                        r0 = __fmaf_rn(wv.z, a.z, r0); r1 = __fmaf_rn(wv.w, a.z, r1);
                        s0 = __fmaf_rn(wv.z, a.w, s0); s1 = __fmaf_rn(wv.w, a.w, s1);
                    }
                    __syncwarp();
                    rb0 = r0 + b3lo;
                    rb1 = r1 + b3hi;
                    z3lo = __fmaf_rn(y, s0, rb0);
                    z3hi = __fmaf_rn(y, s1, rb1);
                } else {
                    unsigned f2a = __ballot_sync(0xffffffffu, q0 != (bool)((prevpk >> 2) & 1u));
                    unsigned f2b = __ballot_sync(0xffffffffu, q1 != (bool)((prevpk >> 3) & 1u));
                    if (f2a | f2b) {
                        float su_lo = q0 ? ub0 : -ub0;
                        float sv_lo = q0 ? t0  : -t0;
                        float su_hi = q1 ? ub1 : -ub1;
                        float sv_hi = q1 ? t1  : -t1;
                        for (unsigned m = f2a; m; m &= m - 1u) {
                            int j = __ffs(m) - 1;
                            float cu = __shfl_sync(0xffffffffu, su_lo, j);
                            float cv = __shfl_sync(0xffffffffu, sv_lo, j);
                            float4 wv = pW3f4[(j >> 1) * 32 + l];
                            float wxc = (j & 1) ? wv.z : wv.x;
                            float wyc = (j & 1) ? wv.w : wv.y;
                            rb0 = __fmaf_rn(cu, wxc, rb0); rb1 = __fmaf_rn(cu, wyc, rb1);
                            s0  = __fmaf_rn(cv, wxc, s0);  s1  = __fmaf_rn(cv, wyc, s1);
                        }
                        for (unsigned m = f2b; m; m &= m - 1u) {
                            int jj = (__ffs(m) - 1) + 32;
                            float cu = __shfl_sync(0xffffffffu, su_hi, jj - 32);
                            float cv = __shfl_sync(0xffffffffu, sv_hi, jj - 32);
                            float4 wv = pW3f4[(jj >> 1) * 32 + l];
                            float wxc = (jj & 1) ? wv.z : wv.x;
                            float wyc = (jj & 1) ? wv.w : wv.y;
                            rb0 = __fmaf_rn(cu, wxc, rb0); rb1 = __fmaf_rn(cu, wyc, rb1);
                            s0  = __fmaf_rn(cv, wxc, s0);  s1  = __fmaf_rn(cv, wyc, s1);
                        }
                        z3lo = __fmaf_rn(y, s0, rb0);
                        z3hi = __fmaf_rn(y, s1, rb1);
                    }
                }

                // ---------- level 3 + gy ----------
                bool g0 = z3lo > 0.0f, g1 = z3hi > 0.0f;
                float p = (g0 ? __fmul_rn(w4lo, s0) : 0.0f)
                        + (g1 ? __fmul_rn(w4hi, s1) : 0.0f);
                #pragma unroll
                for (int off = 16; off; off >>= 1)
                    p += __shfl_xor_sync(0xffffffffu, p, off);
                gy = p;

                prevpk = (unsigned)(z1lo > 0.0f)
                       | ((unsigned)(z1hi > 0.0f) << 1)
                       | ((unsigned)q0 << 2) | ((unsigned)q1 << 3)
                       | ((unsigned)g0 << 4) | ((unsigned)g1 << 5);
                force = false;
            }

            // y <- y - 0.1*gy (non-fused to mirror JAX rounding)
            y = __fadd_rn(y, -__fmul_rn(0.1f, gy));
        }

        if (l == 0) out[smp] = y;
    }
}

// ---------------------------------------------------------------------------
// Inputs (metadata order):
//   0:x [B] 1:c [B] 2:W1 [64*3] 3:b1 [64] 4:W2 [64*64] 5:b2 [64]
//   6:W3 [64*64] 7:b3 [64] 8:W4 [64] 9:b4 [1] (unused: gy independent of b4)
// ---------------------------------------------------------------------------
extern "C" void kernel_launch(void* const* d_in, const int* in_sizes, int n_in,
                              void* d_out, int out_size)
{
    const float* x  = (const float*)d_in[0];
    const float* c  = (const float*)d_in[1];
    const float* W1 = (const float*)d_in[2];
    const float* b1 = (const float*)d_in[3];
    const float* W2 = (const float*)d_in[4];
    const float* b2 = (const float*)d_in[5];
    const float* W3 = (const float*)d_in[6];
    const float* b3 = (const float*)d_in[7];
    const float* W4 = (const float*)d_in[8];
    float* out = (float*)d_out;

    const int B = in_sizes[0];   // 8192

    // 1) NN (also resets the work-stealing counter, stream-ordered)
    nn_kernel<<<(B + 7) / 8, 256>>>(c, B);

    // 2) persistent solve: exactly one residency wave (148 SMs x 5 blocks)
    solve_kernel<<<740, 256>>>(x, W1, b1, W2, b2, W3, b3, W4, out, B);
}

// round 12
// speedup vs baseline: 1.2256x; 1.2256x over previous
#include <cuda_runtime.h>
#include <cuda_bf16.h>

#define NB      8192
#define STEPS   50
#define HID     64

// ---------------------------------------------------------------------------
// Fused kernel (R8 structure), TWO samples per warp for 2x ILP on the
// latency-bound step chain. Per-sample math is bit-identical to R8:
// piecewise-linear affine caching + rank-1 incremental mask updates,
// float4-packed weights, one fast-path ballot per step covering BOTH samples.
//
// Phase-ordered smem reuse: buf holds c[8192] during the NN scan, then the
// float4-packed W2|W3 (32 KB either way).
// ---------------------------------------------------------------------------

// Full slow-path update for one sample (warp-uniform entry; ballots inside).
__device__ __forceinline__ void update_sample(
    float& y, float& gy,
    float& t0, float& t1, float& ub0, float& ub1,
    float& s0, float& s1, float& rb0, float& rb1,
    unsigned& prevpk, bool force,
    float a1lo, float a1hi, float wylo, float wyhi,
    float b2lo, float b2hi, float b3lo, float b3hi,
    float w4lo, float w4hi,
    int l, float2* act, const float4* act4,
    const float4* pW2f4, const float4* pW3f4)
{
    const int o0 = l, o1 = l + 32;
    float z1lo = __fmaf_rn(y, wylo, a1lo);
    float z1hi = __fmaf_rn(y, wyhi, a1hi);
    float z2lo = __fmaf_rn(y, t0, ub0);
    float z2hi = __fmaf_rn(y, t1, ub1);
    float z3lo = __fmaf_rn(y, s0, rb0);
    float z3hi = __fmaf_rn(y, s1, rb1);

    // ---------- level 1 ----------
    unsigned f1a = __ballot_sync(0xffffffffu, (z1lo > 0.0f) != (bool)(prevpk & 1u));
    unsigned f1b = __ballot_sync(0xffffffffu, (z1hi > 0.0f) != (bool)((prevpk >> 1) & 1u));
    int n1 = __popc(f1a) + __popc(f1b);
    bool full1 = force || (n1 > 6);
    if (full1) {
        bool p0 = z1lo > 0.0f, p1 = z1hi > 0.0f;
        act[o0] = make_float2(p0 ? a1lo : 0.0f, p0 ? wylo : 0.0f);
        act[o1] = make_float2(p1 ? a1hi : 0.0f, p1 ? wyhi : 0.0f);
        __syncwarp();
        float u0 = 0.f, u1 = 0.f;
        t0 = t1 = 0.f;
        #pragma unroll 8
        for (int q = 0; q < 32; ++q) {
            float4 a  = act4[q];
            float4 wv = pW2f4[q * 32 + l];
            u0 = __fmaf_rn(wv.x, a.x, u0); u1 = __fmaf_rn(wv.y, a.x, u1);
            t0 = __fmaf_rn(wv.x, a.y, t0); t1 = __fmaf_rn(wv.y, a.y, t1);
            u0 = __fmaf_rn(wv.z, a.z, u0); u1 = __fmaf_rn(wv.w, a.z, u1);
            t0 = __fmaf_rn(wv.z, a.w, t0); t1 = __fmaf_rn(wv.w, a.w, t1);
        }
        __syncwarp();
        ub0 = u0 + b2lo;
        ub1 = u1 + b2hi;
    } else if (n1) {
        // rank-1 AXPY per flipped m1 bit (sign = NEW state)
        float sa_lo = (z1lo > 0.0f) ? a1lo : -a1lo;
        float st_lo = (z1lo > 0.0f) ? wylo : -wylo;
        float sa_hi = (z1hi > 0.0f) ? a1hi : -a1hi;
        float st_hi = (z1hi > 0.0f) ? wyhi : -wyhi;
        for (unsigned m = f1a; m; m &= m - 1u) {
            int k = __ffs(m) - 1;
            float ca = __shfl_sync(0xffffffffu, sa_lo, k);
            float ct = __shfl_sync(0xffffffffu, st_lo, k);
            float4 wv = pW2f4[(k >> 1) * 32 + l];
            float wxc = (k & 1) ? wv.z : wv.x;
            float wyc = (k & 1) ? wv.w : wv.y;
            ub0 = __fmaf_rn(ca, wxc, ub0); ub1 = __fmaf_rn(ca, wyc, ub1);
            t0  = __fmaf_rn(ct, wxc, t0);  t1  = __fmaf_rn(ct, wyc, t1);
        }
        for (unsigned m = f1b; m; m &= m - 1u) {
            int kk = (__ffs(m) - 1) + 32;
            float ca = __shfl_sync(0xffffffffu, sa_hi, kk - 32);
            float ct = __shfl_sync(0xffffffffu, st_hi, kk - 32);
            float4 wv = pW2f4[(kk >> 1) * 32 + l];
            float wxc = (kk & 1) ? wv.z : wv.x;
            float wyc = (kk & 1) ? wv.w : wv.y;
            ub0 = __fmaf_rn(ca, wxc, ub0); ub1 = __fmaf_rn(ca, wyc, ub1);
            t0  = __fmaf_rn(ct, wxc, t0);  t1  = __fmaf_rn(ct, wyc, t1);
        }
    }
    const bool l1ran = full1 || (n1 > 0);
    if (l1ran) {
        z2lo = __fmaf_rn(y, t0, ub0);
        z2hi = __fmaf_rn(y, t1, ub1);
    }

    // ---------- level 2 ----------
    bool q0 = z2lo > 0.0f, q1 = z2hi > 0.0f;
    if (l1ran) {
        act[o0] = make_float2(q0 ? ub0 : 0.0f, q0 ? t0 : 0.0f);
        act[o1] = make_float2(q1 ? ub1 : 0.0f, q1 ? t1 : 0.0f);
        __syncwarp();
        float r0 = 0.f, r1 = 0.f;
        s0 = s1 = 0.f;
        #pragma unroll 8
        for (int q = 0; q < 32; ++q) {
            float4 a  = act4[q];
            float4 wv = pW3f4[q * 32 + l];
            r0 = __fmaf_rn(wv.x, a.x, r0); r1 = __fmaf_rn(wv.y, a.x, r1);
            s0 = __fmaf_rn(wv.x, a.y, s0); s1 = __fmaf_rn(wv.y, a.y, s1);
            r0 = __fmaf_rn(wv.z, a.z, r0); r1 = __fmaf_rn(wv.w, a.z, r1);
            s0 = __fmaf_rn(wv.z, a.w, s0); s1 = __fmaf_rn(wv.w, a.w, s1);
        }
        __syncwarp();
        rb0 = r0 + b3lo;
        rb1 = r1 + b3hi;
        z3lo = __fmaf_rn(y, s0, rb0);
        z3hi = __fmaf_rn(y, s1, rb1);
    } else {
        unsigned f2a = __ballot_sync(0xffffffffu, q0 != (bool)((prevpk >> 2) & 1u));
        unsigned f2b = __ballot_sync(0xffffffffu, q1 != (bool)((prevpk >> 3) & 1u));
        if (f2a | f2b) {
            float su_lo = q0 ? ub0 : -ub0;
            float sv_lo = q0 ? t0  : -t0;
            float su_hi = q1 ? ub1 : -ub1;
            float sv_hi = q1 ? t1  : -t1;
            for (unsigned m = f2a; m; m &= m - 1u) {
                int j = __ffs(m) - 1;
                float cu = __shfl_sync(0xffffffffu, su_lo, j);
                float cv = __shfl_sync(0xffffffffu, sv_lo, j);
                float4 wv = pW3f4[(j >> 1) * 32 + l];
                float wxc = (j & 1) ? wv.z : wv.x;
                float wyc = (j & 1) ? wv.w : wv.y;
                rb0 = __fmaf_rn(cu, wxc, rb0); rb1 = __fmaf_rn(cu, wyc, rb1);
                s0  = __fmaf_rn(cv, wxc, s0);  s1  = __fmaf_rn(cv, wyc, s1);
            }
            for (unsigned m = f2b; m; m &= m - 1u) {
                int jj = (__ffs(m) - 1) + 32;
                float cu = __shfl_sync(0xffffffffu, su_hi, jj - 32);
                float cv = __shfl_sync(0xffffffffu, sv_hi, jj - 32);
                float4 wv = pW3f4[(jj >> 1) * 32 + l];
                float wxc = (jj & 1) ? wv.z : wv.x;
                float wyc = (jj & 1) ? wv.w : wv.y;
                rb0 = __fmaf_rn(cu, wxc, rb0); rb1 = __fmaf_rn(cu, wyc, rb1);
                s0  = __fmaf_rn(cv, wxc, s0);  s1  = __fmaf_rn(cv, wyc, s1);
            }
            z3lo = __fmaf_rn(y, s0, rb0);
            z3hi = __fmaf_rn(y, s1, rb1);
        }
    }

    // ---------- level 3 + gy ----------
    bool g0 = z3lo > 0.0f, g1 = z3hi > 0.0f;
    float p = (g0 ? __fmul_rn(w4lo, s0) : 0.0f)
            + (g1 ? __fmul_rn(w4hi, s1) : 0.0f);
    #pragma unroll
    for (int off = 16; off; off >>= 1)
        p += __shfl_xor_sync(0xffffffffu, p, off);
    gy = p;

    prevpk = (unsigned)(z1lo > 0.0f)
           | ((unsigned)(z1hi > 0.0f) << 1)
           | ((unsigned)q0 << 2) | ((unsigned)q1 << 3)
           | ((unsigned)g0 << 4) | ((unsigned)g1 << 5);
}

__global__ void __launch_bounds__(256, 3) solve_kernel(
    const float* __restrict__ x,  const float* __restrict__ c,
    const float* __restrict__ W1, const float* __restrict__ b1,
    const float* __restrict__ W2, const float* __restrict__ b2,
    const float* __restrict__ W3, const float* __restrict__ b3,
    const float* __restrict__ W4,
    float* __restrict__ out, int B)
{
    __shared__ __align__(16) char buf[32768];   // phase A: c[8192]; phase B: W2f4|W3f4
    __shared__ float4 sAct4[8][HID / 2];

    const int tid = threadIdx.x;
    const int w = tid >> 5, l = tid & 31;
    const int sA = min((blockIdx.x * 8 + w) * 2,     B - 1);
    const int sB = min((blockIdx.x * 8 + w) * 2 + 1, B - 1);

    // ---------------- phase A: stage c, dual NN scan per warp ----------------
    float* sc = (float*)buf;
    {
        const float4* c4 = (const float4*)c;
        float4* s4 = (float4*)buf;
        #pragma unroll
        for (int i = 0; i < NB / 4 / 256; ++i) s4[tid + i * 256] = c4[tid + i * 256];
    }
    __syncthreads();

    const float ciA = sc[sA], ciB = sc[sB];
    float c0A, c0B;
    {
        const float2* sc2 = (const float2*)buf;
        float bxA = 3.0e38f, byA = 3.0e38f, bxB = 3.0e38f, byB = 3.0e38f;
        int   jxA = 0, jyA = 1, jxB = 0, jyB = 1;
        #pragma unroll 4
        for (int q = 0; q < NB / 64; ++q) {
            float2 v = sc2[q * 32 + l];
            int j = (q * 32 + l) * 2;
            float dxA = fabsf(ciA - v.x); if (j == sA)     dxA = 3.0e38f;
            if (dxA < bxA) { bxA = dxA; jxA = j; }
            float dyA = fabsf(ciA - v.y); if (j + 1 == sA) dyA = 3.0e38f;
            if (dyA < byA) { byA = dyA; jyA = j + 1; }
            float dxB = fabsf(ciB - v.x); if (j == sB)     dxB = 3.0e38f;
            if (dxB < bxB) { bxB = dxB; jxB = j; }
            float dyB = fabsf(ciB - v.y); if (j + 1 == sB) dyB = 3.0e38f;
            if (dyB < byB) { byB = dyB; jyB = j + 1; }
        }
        float bestA = bxA; int bjA = jxA;
        if (byA < bestA || (byA == bestA && jyA < bjA)) { bestA = byA; bjA = jyA; }
        float bestB = bxB; int bjB = jxB;
        if (byB < bestB || (byB == bestB && jyB < bjB)) { bestB = byB; bjB = jyB; }
        #pragma unroll
        for (int off = 16; off; off >>= 1) {
            float oa = __shfl_xor_sync(0xffffffffu, bestA, off);
            int   ja = __shfl_xor_sync(0xffffffffu, bjA,   off);
            if (oa < bestA || (oa == bestA && ja < bjA)) { bestA = oa; bjA = ja; }
            float ob = __shfl_xor_sync(0xffffffffu, bestB, off);
            int   jb = __shfl_xor_sync(0xffffffffu, bjB,   off);
            if (ob < bestB || (ob == bestB && jb < bjB)) { bestB = ob; bjB = jb; }
        }
        c0A = sc[bjA];
        c0B = sc[bjB];
    }
    __syncthreads();   // everyone done reading sc

    // ---------------- phase B: pack weights into float4 layout ----------------
    float4* pW2f4 = (float4*)buf;
    float4* pW3f4 = (float4*)(buf + 16384);
    for (int idx = tid; idx < HID * HID; idx += 256) {
        int o = idx >> 6, k = idx & 63;
        int slot = (k >> 1) * 32 + (o & 31);
        int comp = (k & 1) * 2 + (o >> 5);
        ((float*)&pW2f4[slot])[comp] = W2[idx];
        ((float*)&pW3f4[slot])[comp] = W3[idx];
    }
    __syncthreads();

    // ---------------- per-lane constants ----------------
    const int o0 = l, o1 = l + 32;
    const float w1xlo = W1[o0 * 3 + 0], w1clo = W1[o0 * 3 + 2];
    const float w1xhi = W1[o1 * 3 + 0], w1chi = W1[o1 * 3 + 2];
    const float wylo  = W1[o0 * 3 + 1], wyhi  = W1[o1 * 3 + 1];
    const float b1lo  = b1[o0], b1hi = b1[o1];
    const float b2lo  = b2[o0], b2hi = b2[o1];
    const float b3lo  = b3[o0], b3hi = b3[o1];
    const float w4lo  = W4[o0], w4hi = W4[o1];

    const float xA = x[sA], xB = x[sB];
    const float a1loA = __fmaf_rn(w1xlo, xA, __fmaf_rn(w1clo, c0A, b1lo));
    const float a1hiA = __fmaf_rn(w1xhi, xA, __fmaf_rn(w1chi, c0A, b1hi));
    const float a1loB = __fmaf_rn(w1xlo, xB, __fmaf_rn(w1clo, c0B, b1lo));
    const float a1hiB = __fmaf_rn(w1xhi, xB, __fmaf_rn(w1chi, c0B, b1hi));

    float2* act = (float2*)sAct4[w];
    const float4* act4 = (const float4*)sAct4[w];

    // ---------------- dual-sample state ----------------
    float yA = 0.f, gyA = 0.f, t0A = 0.f, t1A = 0.f, ub0A = 0.f, ub1A = 0.f;
    float s0A = 0.f, s1A = 0.f, rb0A = 0.f, rb1A = 0.f;
    float yB = 0.f, gyB = 0.f, t0B = 0.f, t1B = 0.f, ub0B = 0.f, ub1B = 0.f;
    float s0B = 0.f, s1B = 0.f, rb0B = 0.f, rb1B = 0.f;
    unsigned prevA = 0u, prevB = 0u;
    bool force = true;

    for (int step = 0; step < STEPS; ++step) {
        // speculative affine evaluation, both samples (12 independent FMA)
        float z1loA = __fmaf_rn(yA, wylo, a1loA);
        float z1hiA = __fmaf_rn(yA, wyhi, a1hiA);
        float z2loA = __fmaf_rn(yA, t0A, ub0A);
        float z2hiA = __fmaf_rn(yA, t1A, ub1A);
        float z3loA = __fmaf_rn(yA, s0A, rb0A);
        float z3hiA = __fmaf_rn(yA, s1A, rb1A);
        float z1loB = __fmaf_rn(yB, wylo, a1loB);
        float z1hiB = __fmaf_rn(yB, wyhi, a1hiB);
        float z2loB = __fmaf_rn(yB, t0B, ub0B);
        float z2hiB = __fmaf_rn(yB, t1B, ub1B);
        float z3loB = __fmaf_rn(yB, s0B, rb0B);
        float z3hiB = __fmaf_rn(yB, s1B, rb1B);

        unsigned pkA = (unsigned)(z1loA > 0.0f)
                     | ((unsigned)(z1hiA > 0.0f) << 1)
                     | ((unsigned)(z2loA > 0.0f) << 2)
                     | ((unsigned)(z2hiA > 0.0f) << 3)
                     | ((unsigned)(z3loA > 0.0f) << 4)
                     | ((unsigned)(z3hiA > 0.0f) << 5);
        unsigned pkB = (unsigned)(z1loB > 0.0f)
                     | ((unsigned)(z1hiB > 0.0f) << 1)
                     | ((unsigned)(z2loB > 0.0f) << 2)
                     | ((unsigned)(z2hiB > 0.0f) << 3)
                     | ((unsigned)(z3loB > 0.0f) << 4)
                     | ((unsigned)(z3hiB > 0.0f) << 5);

        bool chgA = force | (pkA != prevA);
        bool chgB = force | (pkB != prevB);
        // ONE fast-path ballot for both samples
        if (__ballot_sync(0xffffffffu, chgA | chgB)) {
            if (__ballot_sync(0xffffffffu, chgA))
                update_sample(yA, gyA, t0A, t1A, ub0A, ub1A, s0A, s1A, rb0A, rb1A,
                              prevA, force, a1loA, a1hiA, wylo, wyhi,
                              b2lo, b2hi, b3lo, b3hi, w4lo, w4hi,
                              l, act, act4, pW2f4, pW3f4);
            if (__ballot_sync(0xffffffffu, chgB))
                update_sample(yB, gyB, t0B, t1B, ub0B, ub1B, s0B, s1B, rb0B, rb1B,
                              prevB, force, a1loB, a1hiB, wylo, wyhi,
                              b2lo, b2hi, b3lo, b3hi, w4lo, w4hi,
                              l, act, act4, pW2f4, pW3f4);
            force = false;
        }

        // y <- y - 0.1*gy (non-fused to mirror JAX rounding), both samples
        yA = __fadd_rn(yA, -__fmul_rn(0.1f, gyA));
        yB = __fadd_rn(yB, -__fmul_rn(0.1f, gyB));
    }

    if (l == 0) {
        out[sA] = yA;
        if (sB != sA) out[sB] = yB;
    }
}

// ---------------------------------------------------------------------------
// Inputs (metadata order):
//   0:x [B] 1:c [B] 2:W1 [64*3] 3:b1 [64] 4:W2 [64*64] 5:b2 [64]
//   6:W3 [64*64] 7:b3 [64] 8:W4 [64] 9:b4 [1] (unused: gy independent of b4)
// ---------------------------------------------------------------------------
extern "C" void kernel_launch(void* const* d_in, const int* in_sizes, int n_in,
                              void* d_out, int out_size)
{
    const float* x  = (const float*)d_in[0];
    const float* c  = (const float*)d_in[1];
    const float* W1 = (const float*)d_in[2];
    const float* b1 = (const float*)d_in[3];
    const float* W2 = (const float*)d_in[4];
    const float* b2 = (const float*)d_in[5];
    const float* W3 = (const float*)d_in[6];
    const float* b3 = (const float*)d_in[7];
    const float* W4 = (const float*)d_in[8];
    float* out = (float*)d_out;

    const int B = in_sizes[0];   // 8192

    // fused kernel: NN + solve, 2 samples per warp, 16 per 256-thread block
    solve_kernel<<<(B + 15) / 16, 256>>>(x, c, W1, b1, W2, b2, W3, b3, W4, out, B);
}